// round 1
// baseline (speedup 1.0000x reference)
#include <cuda_runtime.h>
#include <cstdint>

// Problem constants
#define BB 96     // batch
#define HH 100    // history length
#define NN 128    // candidates (broadcast only)
#define DD 768    // embedding dim
#define AA 256    // attention dim

// ---------------- scratch (no allocations allowed) ----------------
__device__ float g_neigh[BB * DD];          // mean of first 96 history rows
__device__ float g_bias [BB * DD];          // neigh @ W_l^T + b_l
__device__ float g_gcn  [BB * HH * DD];     // main GEMM output (29.5 MB)
__device__ float g_Q    [BB * AA];
__device__ float g_P    [BB * DD];          // W_K^T @ Q  (folds K away)
__device__ float g_alpha[BB * HH];          // scores then softmax weights
__device__ float g_outb [BB * DD];          // attention-combined user output

// ---------------- packed fp32x2 helpers (Blackwell) ----------------
__device__ __forceinline__ unsigned long long pk2(float x) {
    unsigned long long r;
    asm("mov.b64 %0, {%1, %1};" : "=l"(r) : "f"(x));
    return r;
}
__device__ __forceinline__ void ffma2(unsigned long long& d,
                                      unsigned long long a,
                                      unsigned long long b) {
    asm("fma.rn.f32x2 %0, %1, %2, %0;" : "+l"(d) : "l"(a), "l"(b));
}
__device__ __forceinline__ float2 up2(unsigned long long v) {
    float2 r;
    asm("mov.b64 {%0, %1}, %2;" : "=f"(r.x), "=f"(r.y) : "l"(v));
    return r;
}

// ---------------- 1) neigh = mean_h<96 hist[b,h,:] ----------------
__global__ void k_neigh(const float* __restrict__ hist) {
    int b = blockIdx.x;
    int d = threadIdx.x;                       // 768 threads
    const float* p = hist + (size_t)b * HH * DD + d;
    float s = 0.f;
#pragma unroll 8
    for (int h = 0; h < BB; ++h) s += p[h * DD];
    g_neigh[b * DD + d] = s * (1.0f / BB);
}

// ---------------- 2/3) GEMM  C(M,768) = A(M,768) @ B(768,768)^T + bias
// Both operands are K-contiguous row-major ("TN" dot-product GEMM).
// MODE 0: bias[n]               (b_l vector)
// MODE 1: bias[(m/HH)*DD + n]   (per-batch gcn bias)
template <int MODE>
__global__ __launch_bounds__(256, 2)
void k_gemm768(const float* __restrict__ Am, const float* __restrict__ Bm,
               float* __restrict__ Cm, const float* __restrict__ bias, int M) {
    __shared__ float As[8][128];
    __shared__ float Bs[8][128];

    const int tid = threadIdx.x;
    const int bm = blockIdx.y, bn = blockIdx.x;
    const int tx = tid & 15, ty = tid >> 4;

    // load indexing: each thread brings one float4 of A and one of B per k-tile
    const int lr = tid >> 1;           // 0..127 (tile row)
    const int lc = (tid & 1) * 4;      // 0 or 4 (k offset)

    const int am = bm * 128 + lr;
    const bool a_ok = (am < M);
    const float4* Ag = (const float4*)(Am + (size_t)(a_ok ? am : 0) * DD);
    const float4* Bg = (const float4*)(Bm + (size_t)(bn * 128 + lr) * DD);

    unsigned long long acc[8][4];
#pragma unroll
    for (int i = 0; i < 8; ++i)
#pragma unroll
        for (int j = 0; j < 4; ++j) acc[i][j] = 0ULL;

    for (int k0 = 0; k0 < DD; k0 += 8) {
        float4 av = a_ok ? Ag[(k0 + lc) >> 2] : make_float4(0.f, 0.f, 0.f, 0.f);
        float4 bv = Bg[(k0 + lc) >> 2];
        As[lc + 0][lr] = av.x; As[lc + 1][lr] = av.y;
        As[lc + 2][lr] = av.z; As[lc + 3][lr] = av.w;
        Bs[lc + 0][lr] = bv.x; Bs[lc + 1][lr] = bv.y;
        Bs[lc + 2][lr] = bv.z; Bs[lc + 3][lr] = bv.w;
        __syncthreads();

#pragma unroll
        for (int kk = 0; kk < 8; ++kk) {
            float4 a0 = *(const float4*)&As[kk][ty * 8];
            float4 a1 = *(const float4*)&As[kk][ty * 8 + 4];
            const unsigned long long* b2 =
                (const unsigned long long*)&Bs[kk][tx * 8];
            unsigned long long bb0 = b2[0], bb1 = b2[1], bb2 = b2[2], bb3 = b2[3];
            float a_[8] = {a0.x, a0.y, a0.z, a0.w, a1.x, a1.y, a1.z, a1.w};
#pragma unroll
            for (int i = 0; i < 8; ++i) {
                unsigned long long ai = pk2(a_[i]);
                ffma2(acc[i][0], ai, bb0);
                ffma2(acc[i][1], ai, bb1);
                ffma2(acc[i][2], ai, bb2);
                ffma2(acc[i][3], ai, bb3);
            }
        }
        __syncthreads();
    }

#pragma unroll
    for (int i = 0; i < 8; ++i) {
        int m = bm * 128 + ty * 8 + i;
        if (m >= M) continue;
        const float* brow = (MODE == 0) ? bias : (bias + (size_t)(m / HH) * DD);
        float* crow = Cm + (size_t)m * DD + bn * 128 + tx * 8;
#pragma unroll
        for (int j = 0; j < 4; ++j) {
            float2 v = up2(acc[i][j]);
            int n = bn * 128 + tx * 8 + 2 * j;
            crow[2 * j + 0] = v.x + brow[n + 0];
            crow[2 * j + 1] = v.y + brow[n + 1];
        }
    }
}

// ---------------- 4) Q[b,a] = gcn[b,0,:] . W_Q[a,:] + b_Q[a] (warp/dot)
__global__ void k_q(const float* __restrict__ WQ, const float* __restrict__ bQ) {
    int w = (blockIdx.x * blockDim.x + threadIdx.x) >> 5;
    int lane = threadIdx.x & 31;
    if (w >= BB * AA) return;
    int b = w / AA, a = w % AA;
    const float* u  = g_gcn + (size_t)b * HH * DD;   // h = 0 row
    const float* wq = WQ + (size_t)a * DD;
    float s = 0.f;
#pragma unroll 6
    for (int d = lane; d < DD; d += 32) s += u[d] * wq[d];
#pragma unroll
    for (int o = 16; o; o >>= 1) s += __shfl_down_sync(0xffffffffu, s, o);
    if (lane == 0) g_Q[b * AA + a] = s + bQ[a];
}

// ---------------- 5) P[b,d] = sum_a Q[b,a] * W_K[a,d] ----------------
__global__ void k_p(const float* __restrict__ WK) {
    int i = blockIdx.x * blockDim.x + threadIdx.x;   // BB*DD threads
    int b = i / DD, d = i - b * DD;
    const float* q = g_Q + b * AA;
    float s = 0.f;
#pragma unroll 8
    for (int a = 0; a < AA; ++a) s += q[a] * WK[(size_t)a * DD + d];
    g_P[i] = s;
}

// ---------------- 6) scores[b,h] = gcn[b,h,:] . P[b,:] / 16 ----------
__global__ void k_scores() {
    int w = (blockIdx.x * blockDim.x + threadIdx.x) >> 5;
    int lane = threadIdx.x & 31;
    if (w >= BB * HH) return;
    int b = w / HH, h = w - b * HH;
    const float* g = g_gcn + ((size_t)b * HH + h) * DD;
    const float* p = g_P + (size_t)b * DD;
    float s = 0.f;
#pragma unroll 6
    for (int d = lane; d < DD; d += 32) s += g[d] * p[d];
#pragma unroll
    for (int o = 16; o; o >>= 1) s += __shfl_down_sync(0xffffffffu, s, o);
    if (lane == 0) g_alpha[w] = s * (1.0f / 16.0f);
}

// ---------------- 7) softmax over h (per batch) ----------------------
__global__ void k_softmax() {
    __shared__ float red[4];
    int b = blockIdx.x, t = threadIdx.x;   // 128 threads
    float v = (t < HH) ? g_alpha[b * HH + t] : -1e30f;
    float m = v;
#pragma unroll
    for (int o = 16; o; o >>= 1) m = fmaxf(m, __shfl_xor_sync(0xffffffffu, m, o));
    if ((t & 31) == 0) red[t >> 5] = m;
    __syncthreads();
    float bm = fmaxf(fmaxf(red[0], red[1]), fmaxf(red[2], red[3]));
    float e = (t < HH) ? __expf(v - bm) : 0.f;
    float s = e;
#pragma unroll
    for (int o = 16; o; o >>= 1) s += __shfl_xor_sync(0xffffffffu, s, o);
    __syncthreads();
    if ((t & 31) == 0) red[t >> 5] = s;
    __syncthreads();
    float bs = red[0] + red[1] + red[2] + red[3];
    if (t < HH) g_alpha[b * HH + t] = e / bs;
}

// ---------------- 8) outb[b,d] = sum_h alpha[b,h]*gcn[b,h,d] ---------
__global__ void k_combine() {
    __shared__ float al[HH];
    int b = blockIdx.x / 6, c = blockIdx.x % 6;
    int t = threadIdx.x;                     // 128 threads
    if (t < HH) al[t] = g_alpha[b * HH + t];
    __syncthreads();
    int d = c * 128 + t;
    const float* g = g_gcn + (size_t)b * HH * DD + d;
    float s = 0.f;
#pragma unroll 10
    for (int h = 0; h < HH; ++h) s += al[h] * g[h * DD];
    g_outb[b * DD + d] = s;
}

// ---------------- 9) broadcast to (B, N, D) --------------------------
__global__ void k_bcast(float4* __restrict__ out) {
    int i = blockIdx.x * blockDim.x + threadIdx.x;   // BB*NN*DD/4 threads
    const int D4 = DD / 4;
    int d4 = i % D4;
    int b = i / (D4 * NN);
    out[i] = ((const float4*)g_outb)[b * D4 + d4];
}

// ---------------- launch --------------------------------------------
extern "C" void kernel_launch(void* const* d_in, const int* in_sizes, int n_in,
                              void* d_out, int out_size) {
    (void)in_sizes; (void)n_in; (void)out_size;
    const float* hist = (const float*)d_in[0];
    // d_in[1] = candidate_news_representation (unused, shape only)
    const float* Wl = (const float*)d_in[2];
    const float* bl = (const float*)d_in[3];
    const float* Wr = (const float*)d_in[4];
    const float* WK = (const float*)d_in[5];
    const float* WQ = (const float*)d_in[6];
    const float* bQ = (const float*)d_in[7];

    void *p_neigh, *p_bias, *p_gcn;
    cudaGetSymbolAddress(&p_neigh, g_neigh);
    cudaGetSymbolAddress(&p_bias, g_bias);
    cudaGetSymbolAddress(&p_gcn, g_gcn);

    k_neigh<<<BB, DD>>>(hist);
    k_gemm768<0><<<dim3(6, 1), 256>>>((const float*)p_neigh, Wl,
                                      (float*)p_bias, bl, BB);
    k_gemm768<1><<<dim3(6, (BB * HH + 127) / 128), 256>>>(
        hist, Wr, (float*)p_gcn, (const float*)p_bias, BB * HH);
    k_q<<<(BB * AA * 32) / 256, 256>>>(WQ, bQ);
    k_p<<<(BB * DD) / 256, 256>>>(WK);
    k_scores<<<(BB * HH * 32) / 256, 256>>>();
    k_softmax<<<BB, 128>>>();
    k_combine<<<BB * 6, 128>>>();
    k_bcast<<<(BB * NN * DD / 4) / 256, 256>>>((float4*)d_out);
}

// round 4
// speedup vs baseline: 1.2647x; 1.2647x over previous
#include <cuda_runtime.h>
#include <cuda_bf16.h>
#include <cstdint>

#define BB 96
#define HH 100
#define NN 128
#define DD 768
#define AA 256

#define K2 2304          // 3 * DD (hi|lo|hi concat)
#define BK 64            // k-tile (128 bytes bf16)
#define NIT (K2 / BK)    // 36 mainloop iterations
#define STAGE_BYTES 32768

// ---------------- scratch ----------------
__device__ float g_neigh[BB * DD];
__device__ float g_bias [BB * DD];
__device__ float g_gcn  [BB * HH * DD];
__device__ float g_Q    [BB * AA];
__device__ float g_P    [BB * DD];
__device__ float g_alpha[BB * HH];
__device__ float g_outb [BB * DD];
__device__ __nv_bfloat16 g_Abig[BB * HH * K2];   // 44.2 MB
__device__ __nv_bfloat16 g_Bbig[DD * K2];        // 3.4 MB

// ---------------- helpers ----------------
__device__ __forceinline__ uint32_t smem_u32(const void* p) {
    uint32_t a;
    asm("{ .reg .u64 t; cvta.to.shared.u64 t, %1; cvt.u32.u64 %0, t; }"
        : "=r"(a) : "l"(p));
    return a;
}
#define CP_ASYNC16(saddr, gptr) \
    asm volatile("cp.async.cg.shared.global [%0], [%1], 16;" :: "r"(saddr), "l"(gptr))
#define CP_COMMIT() asm volatile("cp.async.commit_group;" ::: "memory")
#define CP_WAIT1()  asm volatile("cp.async.wait_group 1;" ::: "memory")

#define LDSM_X4(r0, r1, r2, r3, addr) \
    asm volatile("ldmatrix.sync.aligned.m8n8.x4.shared.b16 {%0,%1,%2,%3}, [%4];" \
                 : "=r"(r0), "=r"(r1), "=r"(r2), "=r"(r3) : "r"(addr))
#define MMA_BF16(c, a, b) \
    asm volatile("mma.sync.aligned.m16n8k16.row.col.f32.bf16.bf16.f32 " \
                 "{%0,%1,%2,%3}, {%4,%5,%6,%7}, {%8,%9}, {%0,%1,%2,%3};" \
                 : "+f"((c)[0]), "+f"((c)[1]), "+f"((c)[2]), "+f"((c)[3]) \
                 : "r"((a)[0]), "r"((a)[1]), "r"((a)[2]), "r"((a)[3]), \
                   "r"((b)[0]), "r"((b)[1]))

// ---------------- fp32 -> bf16 split into concat layout ----------------
// out row pitch K2; writes hi at +0 and +o_hi2, lo at +o_lo.
__global__ void k_split3(const float* __restrict__ x, __nv_bfloat16* __restrict__ out,
                         int n4, int o_hi2, int o_lo) {
    int i = blockIdx.x * blockDim.x + threadIdx.x;
    if (i >= n4) return;
    int j = i * 4;
    int m = j / DD, k = j - m * DD;
    float4 v = ((const float4*)x)[i];
    __nv_bfloat162 h01 = __floats2bfloat162_rn(v.x, v.y);
    __nv_bfloat162 h23 = __floats2bfloat162_rn(v.z, v.w);
    float2 f01 = __bfloat1622float2(h01);
    float2 f23 = __bfloat1622float2(h23);
    __nv_bfloat162 l01 = __floats2bfloat162_rn(v.x - f01.x, v.y - f01.y);
    __nv_bfloat162 l23 = __floats2bfloat162_rn(v.z - f23.x, v.w - f23.y);
    __nv_bfloat16* base = out + (size_t)m * K2 + k;
    ((__nv_bfloat162*)base)[0] = h01;
    ((__nv_bfloat162*)base)[1] = h23;
    ((__nv_bfloat162*)(base + o_hi2))[0] = h01;
    ((__nv_bfloat162*)(base + o_hi2))[1] = h23;
    ((__nv_bfloat162*)(base + o_lo))[0] = l01;
    ((__nv_bfloat162*)(base + o_lo))[1] = l23;
}

// ---------------- main GEMM: C(9600,768) = A'(.,2304) @ B'(768,2304)^T + bias
__global__ void __launch_bounds__(256, 1)
k_gemm_mma(const __nv_bfloat16* __restrict__ Ab, const __nv_bfloat16* __restrict__ Bb,
           const float* __restrict__ bias, float* __restrict__ C) {
    extern __shared__ char smem[];
    const int tid = threadIdx.x;
    const int wid = tid >> 5, lane = tid & 31;
    const int tm = blockIdx.y, tn = blockIdx.x;
    const int wm = wid >> 2, wn = wid & 3;       // warp grid 2 (M) x 4 (N)

    const uint32_t sbase = smem_u32(smem);

    // cp.async mapping: per stage, A=1024 16B chunks, B=1024; 8 per thread.
    const int row_ld = tid >> 3;                 // base row 0..31 step: +32 per i
    const int c_ld = tid & 7;                    // 16B chunk 0..7

    const __nv_bfloat16* Agp = Ab + (size_t)(tm * 128) * K2;
    const __nv_bfloat16* Bgp = Bb + (size_t)(tn * 128) * K2;

#define ISSUE(slot, k0) do {                                                  \
    uint32_t sA = sbase + (slot) * STAGE_BYTES;                               \
    uint32_t sB = sA + 16384;                                                 \
    _Pragma("unroll") for (int i = 0; i < 4; ++i) {                           \
        int r = row_ld + 32 * i;                                              \
        uint32_t so = (uint32_t)(r * 128 + ((c_ld ^ (r & 7)) << 4));          \
        CP_ASYNC16(sA + so, Agp + (size_t)r * K2 + (k0) + c_ld * 8);          \
        CP_ASYNC16(sB + so, Bgp + (size_t)r * K2 + (k0) + c_ld * 8);          \
    } } while (0)

    float acc[4][4][4];
#pragma unroll
    for (int mt = 0; mt < 4; ++mt)
#pragma unroll
        for (int nt = 0; nt < 4; ++nt)
#pragma unroll
            for (int r = 0; r < 4; ++r) acc[mt][nt][r] = 0.f;

    ISSUE(0, 0); CP_COMMIT();
    ISSUE(1, BK); CP_COMMIT();

    // ldmatrix per-lane addressing (precompute invariant parts)
    const int arow = wm * 64 + (lane & 15);      // + mt*16
    const int ac_half = lane >> 4;               // 0/1 -> k chunk parity
    const int bsub = lane >> 3;
    const int bn_base = wn * 32 + ((bsub & 2) << 2) + (lane & 7);  // + pair*16
    const int bc_half = bsub & 1;

    for (int it = 0; it < NIT; ++it) {
        CP_WAIT1();
        __syncthreads();
        int nxt = it + 2;
        if (nxt < NIT) ISSUE(nxt % 3, nxt * BK);
        CP_COMMIT();

        const int slot = it % 3;
        const uint32_t sA = sbase + slot * STAGE_BYTES;
        const uint32_t sB = sA + 16384;

#pragma unroll
        for (int ks = 0; ks < 4; ++ks) {
            uint32_t a[4][4];
#pragma unroll
            for (int mt = 0; mt < 4; ++mt) {
                int r = arow + mt * 16;
                int c = ks * 2 + ac_half;
                uint32_t ad = sA + r * 128 + ((c ^ (r & 7)) << 4);
                LDSM_X4(a[mt][0], a[mt][1], a[mt][2], a[mt][3], ad);
            }
            uint32_t b[4][2];
#pragma unroll
            for (int pr = 0; pr < 2; ++pr) {
                int n = bn_base + pr * 16;
                int c = ks * 2 + bc_half;
                uint32_t bd = sB + n * 128 + ((c ^ (n & 7)) << 4);
                // non-trans: thread t <- Bst[n0 + t/4][k0 + 2*(t%4)], matching the
                // m16n8k16 col-major B fragment (k pairs contiguous in memory).
                LDSM_X4(b[2 * pr][0], b[2 * pr][1], b[2 * pr + 1][0], b[2 * pr + 1][1], bd);
            }
#pragma unroll
            for (int mt = 0; mt < 4; ++mt)
#pragma unroll
                for (int nt = 0; nt < 4; ++nt)
                    MMA_BF16(acc[mt][nt], a[mt], b[nt]);
        }
    }

    // ---- epilogue: direct global store + per-batch bias
    const int gid = lane >> 2, tig = lane & 3;
#pragma unroll
    for (int mt = 0; mt < 4; ++mt) {
#pragma unroll
        for (int half = 0; half < 2; ++half) {
            int mg = tm * 128 + wm * 64 + mt * 16 + half * 8 + gid;
            int b = mg / HH;
            const float* brow = bias + (size_t)b * DD + tn * 128 + wn * 32;
            float* crow = C + (size_t)mg * DD + tn * 128 + wn * 32;
#pragma unroll
            for (int nt = 0; nt < 4; ++nt) {
                int col = nt * 8 + tig * 2;
                float2 v;
                v.x = acc[mt][nt][2 * half]     + brow[col];
                v.y = acc[mt][nt][2 * half + 1] + brow[col + 1];
                *(float2*)(crow + col) = v;
            }
        }
    }
}

// ---------------- packed fp32x2 helpers (small bias GEMM) ------------
__device__ __forceinline__ unsigned long long pk2(float x) {
    unsigned long long r;
    asm("mov.b64 %0, {%1, %1};" : "=l"(r) : "f"(x));
    return r;
}
__device__ __forceinline__ void ffma2(unsigned long long& d, unsigned long long a,
                                      unsigned long long b) {
    asm("fma.rn.f32x2 %0, %1, %2, %0;" : "+l"(d) : "l"(a), "l"(b));
}
__device__ __forceinline__ float2 up2(unsigned long long v) {
    float2 r;
    asm("mov.b64 {%0, %1}, %2;" : "=f"(r.x), "=f"(r.y) : "l"(v));
    return r;
}

// ---------------- neigh mean ----------------
__global__ void k_neigh(const float* __restrict__ hist) {
    int b = blockIdx.x;
    int d = threadIdx.x;
    const float* p = hist + (size_t)b * HH * DD + d;
    float s = 0.f;
#pragma unroll 8
    for (int h = 0; h < BB; ++h) s += p[h * DD];
    g_neigh[b * DD + d] = s * (1.0f / BB);
}

// ---------------- small FFMA GEMM: g_bias = neigh @ Wl^T + bl --------
__global__ void __launch_bounds__(256, 2)
k_gemm_bias(const float* __restrict__ Am, const float* __restrict__ Bm,
            float* __restrict__ Cm, const float* __restrict__ bias, int M) {
    __shared__ float As[8][128];
    __shared__ float Bs[8][128];
    const int tid = threadIdx.x;
    const int bm = blockIdx.y, bn = blockIdx.x;
    const int tx = tid & 15, ty = tid >> 4;
    const int lr = tid >> 1;
    const int lc = (tid & 1) * 4;
    const int am = bm * 128 + lr;
    const bool a_ok = (am < M);
    const float4* Ag = (const float4*)(Am + (size_t)(a_ok ? am : 0) * DD);
    const float4* Bg = (const float4*)(Bm + (size_t)(bn * 128 + lr) * DD);

    unsigned long long acc[8][4];
#pragma unroll
    for (int i = 0; i < 8; ++i)
#pragma unroll
        for (int j = 0; j < 4; ++j) acc[i][j] = 0ULL;

    for (int k0 = 0; k0 < DD; k0 += 8) {
        float4 av = a_ok ? Ag[(k0 + lc) >> 2] : make_float4(0.f, 0.f, 0.f, 0.f);
        float4 bv = Bg[(k0 + lc) >> 2];
        As[lc + 0][lr] = av.x; As[lc + 1][lr] = av.y;
        As[lc + 2][lr] = av.z; As[lc + 3][lr] = av.w;
        Bs[lc + 0][lr] = bv.x; Bs[lc + 1][lr] = bv.y;
        Bs[lc + 2][lr] = bv.z; Bs[lc + 3][lr] = bv.w;
        __syncthreads();
#pragma unroll
        for (int kk = 0; kk < 8; ++kk) {
            float4 a0 = *(const float4*)&As[kk][ty * 8];
            float4 a1 = *(const float4*)&As[kk][ty * 8 + 4];
            const unsigned long long* b2 = (const unsigned long long*)&Bs[kk][tx * 8];
            unsigned long long bb0 = b2[0], bb1 = b2[1], bb2 = b2[2], bb3 = b2[3];
            float a_[8] = {a0.x, a0.y, a0.z, a0.w, a1.x, a1.y, a1.z, a1.w};
#pragma unroll
            for (int i = 0; i < 8; ++i) {
                unsigned long long ai = pk2(a_[i]);
                ffma2(acc[i][0], ai, bb0);
                ffma2(acc[i][1], ai, bb1);
                ffma2(acc[i][2], ai, bb2);
                ffma2(acc[i][3], ai, bb3);
            }
        }
        __syncthreads();
    }
#pragma unroll
    for (int i = 0; i < 8; ++i) {
        int m = bm * 128 + ty * 8 + i;
        if (m >= M) continue;
        float* crow = Cm + (size_t)m * DD + bn * 128 + tx * 8;
#pragma unroll
        for (int j = 0; j < 4; ++j) {
            float2 val = up2(acc[i][j]);
            int n = bn * 128 + tx * 8 + 2 * j;
            crow[2 * j + 0] = val.x + bias[n + 0];
            crow[2 * j + 1] = val.y + bias[n + 1];
        }
    }
}

// ---------------- Q = gcn[:,0,:] @ WQ^T + bQ -------------------------
__global__ void k_q2(const float* __restrict__ WQ, const float* __restrict__ bQ) {
    __shared__ float wqs[8][DD];
    int a0 = blockIdx.x * 8;
    for (int i = threadIdx.x; i < 8 * DD; i += 256)
        wqs[i / DD][i % DD] = WQ[(size_t)(a0 + i / DD) * DD + (i % DD)];
    __syncthreads();
    int w = threadIdx.x >> 5, lane = threadIdx.x & 31;
    int a = a0 + w;
    float bq = bQ[a];
    for (int b = 0; b < BB; ++b) {
        const float* u = g_gcn + (size_t)b * HH * DD;
        float s = 0.f;
#pragma unroll 6
        for (int d = lane; d < DD; d += 32) s += u[d] * wqs[w][d];
#pragma unroll
        for (int o = 16; o; o >>= 1) s += __shfl_down_sync(0xffffffffu, s, o);
        if (lane == 0) g_Q[b * AA + a] = s + bq;
    }
}

// ---------------- P[b,d] = sum_a Q[b,a] * W_K[a,d] -------------------
__global__ void k_p(const float* __restrict__ WK) {
    int i = blockIdx.x * blockDim.x + threadIdx.x;
    int b = i / DD, d = i - b * DD;
    const float* q = g_Q + b * AA;
    float s = 0.f;
#pragma unroll 8
    for (int a = 0; a < AA; ++a) s += q[a] * WK[(size_t)a * DD + d];
    g_P[i] = s;
}

// ---------------- scores ----------------
__global__ void k_scores() {
    int w = (blockIdx.x * blockDim.x + threadIdx.x) >> 5;
    int lane = threadIdx.x & 31;
    if (w >= BB * HH) return;
    int b = w / HH, h = w - b * HH;
    const float* g = g_gcn + ((size_t)b * HH + h) * DD;
    const float* p = g_P + (size_t)b * DD;
    float s = 0.f;
#pragma unroll 6
    for (int d = lane; d < DD; d += 32) s += g[d] * p[d];
#pragma unroll
    for (int o = 16; o; o >>= 1) s += __shfl_down_sync(0xffffffffu, s, o);
    if (lane == 0) g_alpha[w] = s * (1.0f / 16.0f);
}

// ---------------- softmax ----------------
__global__ void k_softmax() {
    __shared__ float red[4];
    int b = blockIdx.x, t = threadIdx.x;
    float v = (t < HH) ? g_alpha[b * HH + t] : -1e30f;
    float m = v;
#pragma unroll
    for (int o = 16; o; o >>= 1) m = fmaxf(m, __shfl_xor_sync(0xffffffffu, m, o));
    if ((t & 31) == 0) red[t >> 5] = m;
    __syncthreads();
    float bm = fmaxf(fmaxf(red[0], red[1]), fmaxf(red[2], red[3]));
    float e = (t < HH) ? __expf(v - bm) : 0.f;
    float s = e;
#pragma unroll
    for (int o = 16; o; o >>= 1) s += __shfl_xor_sync(0xffffffffu, s, o);
    __syncthreads();
    if ((t & 31) == 0) red[t >> 5] = s;
    __syncthreads();
    float bs = red[0] + red[1] + red[2] + red[3];
    if (t < HH) g_alpha[b * HH + t] = e / bs;
}

// ---------------- combine ----------------
__global__ void k_combine() {
    __shared__ float al[HH];
    int b = blockIdx.x / 6, c = blockIdx.x % 6;
    int t = threadIdx.x;
    if (t < HH) al[t] = g_alpha[b * HH + t];
    __syncthreads();
    int d = c * 128 + t;
    const float* g = g_gcn + (size_t)b * HH * DD + d;
    float s = 0.f;
#pragma unroll 10
    for (int h = 0; h < HH; ++h) s += al[h] * g[h * DD];
    g_outb[b * DD + d] = s;
}

// ---------------- broadcast ----------------
__global__ void k_bcast(float4* __restrict__ out) {
    int i = blockIdx.x * blockDim.x + threadIdx.x;
    const int D4 = DD / 4;
    int d4 = i % D4;
    int b = i / (D4 * NN);
    out[i] = ((const float4*)g_outb)[b * D4 + d4];
}

// ---------------- launch ----------------
extern "C" void kernel_launch(void* const* d_in, const int* in_sizes, int n_in,
                              void* d_out, int out_size) {
    (void)in_sizes; (void)n_in; (void)out_size;
    const float* hist = (const float*)d_in[0];
    const float* Wl = (const float*)d_in[2];
    const float* bl = (const float*)d_in[3];
    const float* Wr = (const float*)d_in[4];
    const float* WK = (const float*)d_in[5];
    const float* WQ = (const float*)d_in[6];
    const float* bQ = (const float*)d_in[7];

    void *p_neigh, *p_bias, *p_gcn, *p_Ab, *p_Bb;
    cudaGetSymbolAddress(&p_neigh, g_neigh);
    cudaGetSymbolAddress(&p_bias, g_bias);
    cudaGetSymbolAddress(&p_gcn, g_gcn);
    cudaGetSymbolAddress(&p_Ab, g_Abig);
    cudaGetSymbolAddress(&p_Bb, g_Bbig);

    cudaFuncSetAttribute(k_gemm_mma, cudaFuncAttributeMaxDynamicSharedMemorySize, 98304);

    k_neigh<<<BB, DD>>>(hist);
    k_gemm_bias<<<dim3(6, 1), 256>>>((const float*)p_neigh, Wl, (float*)p_bias, bl, BB);
    // A' = [hi | lo | hi], B' = [hi | hi | lo]
    k_split3<<<(BB * HH * DD / 4 + 255) / 256, 256>>>(hist, (__nv_bfloat16*)p_Ab,
                                                      BB * HH * DD / 4, 2 * DD, DD);
    k_split3<<<(DD * DD / 4 + 255) / 256, 256>>>(Wr, (__nv_bfloat16*)p_Bb,
                                                 DD * DD / 4, DD, 2 * DD);
    k_gemm_mma<<<dim3(DD / 128, BB * HH / 128), 256, 98304>>>(
        (const __nv_bfloat16*)p_Ab, (const __nv_bfloat16*)p_Bb,
        (const float*)p_bias, (float*)p_gcn);
    k_q2<<<AA / 8, 256>>>(WQ, bQ);
    k_p<<<(BB * DD) / 256, 256>>>(WK);
    k_scores<<<(BB * HH * 32) / 256, 256>>>();
    k_softmax<<<BB, 128>>>();
    k_combine<<<BB * 6, 128>>>();
    k_bcast<<<(BB * NN * DD / 4) / 256, 256>>>((float4*)d_out);
}

// round 7
// speedup vs baseline: 3.9360x; 3.1122x over previous
#include <cuda_runtime.h>
#include <cstdint>

#define BB 96
#define HH 100
#define NN 128
#define DD 768
#define AA 256
#define LDH (HH * DD)    // 76800, hist batch stride

// ---------------- scratch ----------------
__device__ float g_neigh[BB * DD];
__device__ float g_bias [BB * DD];
__device__ float g_u    [BB * DD];      // gcn row h=0
__device__ float g_Qv   [BB * AA];
__device__ float g_P    [BB * DD];
__device__ float g_R    [BB * DD];
__device__ float g_hbar [BB * DD];
__device__ float g_outb [BB * DD];
__device__ float g_part [6 * BB * DD];  // K-split partials (max KS=6, N=768)
__device__ float g_Wrt  [DD * DD];      // W_r^T
__device__ float g_WKt  [DD * AA];      // W_K^T

// ---------------- transpose: out[C x R] = in[R x C]^T ----------------
__global__ void k_transpose(const float* __restrict__ in, float* __restrict__ out,
                            int R, int C) {
    __shared__ float t[32][33];
    int c0 = blockIdx.x * 32, r0 = blockIdx.y * 32;
    int x = threadIdx.x, y = threadIdx.y;          // 32 x 8
#pragma unroll
    for (int i = 0; i < 4; ++i)
        t[y + 8 * i][x] = in[(size_t)(r0 + y + 8 * i) * C + c0 + x];
    __syncthreads();
#pragma unroll
    for (int i = 0; i < 4; ++i)
        out[(size_t)(c0 + y + 8 * i) * R + r0 + x] = t[x][y + 8 * i];
}

// ---------------- neigh = mean_{h<96} hist[b,h,:] ----------------
__global__ void k_neigh(const float* __restrict__ hist) {
    int b = blockIdx.x, d = threadIdx.x;           // 768 threads
    const float* p = hist + (size_t)b * LDH + d;
    float s = 0.f;
#pragma unroll 8
    for (int h = 0; h < BB; ++h) s += p[h * DD];
    g_neigh[b * DD + d] = s * (1.0f / BB);
}

// ---------------- small GEMM with K-split partials -------------------
// part[ks][96][N] += A[96 x K (lda)] . B-rows[N x K]; grid (N/128, KS)
__global__ void __launch_bounds__(512, 1)
k_sgemm(const float* __restrict__ A, int lda, const float* __restrict__ B,
        float* __restrict__ part, int N, int K) {
    __shared__ float As[32][99];
    __shared__ float Bs[32][129];
    const int tid = threadIdx.x;
    const int nt = blockIdx.x;
    const int KS = gridDim.y;
    const int kc = K / KS;                          // multiple of 32
    const int k0 = blockIdx.y * kc;
    const int nIter = kc / 32;
    const int mIdx = tid >> 4;                      // 0..31 -> m = 3*mIdx + i
    const int nIdx = tid & 15;                      // n = nt*128 + nIdx + 16*j

    float acc[3][8];
#pragma unroll
    for (int i = 0; i < 3; ++i)
#pragma unroll
        for (int j = 0; j < 8; ++j) acc[i][j] = 0.f;

    float2 va[3], vb[4];
#define LOAD_CH(kk) do {                                                      \
    int kb = k0 + (kk) * 32;                                                  \
    _Pragma("unroll") for (int j = 0; j < 3; ++j) {                           \
        int idx = tid + 512 * j; int m = idx >> 4, c = idx & 15;              \
        va[j] = *(const float2*)(A + (size_t)m * lda + kb + 2 * c);           \
    }                                                                         \
    _Pragma("unroll") for (int j = 0; j < 4; ++j) {                           \
        int idx = tid + 512 * j; int n = idx >> 4, c = idx & 15;              \
        vb[j] = *(const float2*)(B + (size_t)(nt * 128 + n) * K + kb + 2 * c);\
    } } while (0)
#define STORE_CH() do {                                                       \
    _Pragma("unroll") for (int j = 0; j < 3; ++j) {                           \
        int idx = tid + 512 * j; int m = idx >> 4, c = idx & 15;              \
        As[2 * c][m] = va[j].x; As[2 * c + 1][m] = va[j].y;                   \
    }                                                                         \
    _Pragma("unroll") for (int j = 0; j < 4; ++j) {                           \
        int idx = tid + 512 * j; int n = idx >> 4, c = idx & 15;              \
        Bs[2 * c][n] = vb[j].x; Bs[2 * c + 1][n] = vb[j].y;                   \
    } } while (0)

    LOAD_CH(0);
    for (int it = 0; it < nIter; ++it) {
        __syncthreads();
        STORE_CH();
        __syncthreads();
        if (it + 1 < nIter) LOAD_CH(it + 1);
#pragma unroll
        for (int k = 0; k < 32; ++k) {
            float a0 = As[k][3 * mIdx], a1 = As[k][3 * mIdx + 1], a2 = As[k][3 * mIdx + 2];
#pragma unroll
            for (int j = 0; j < 8; ++j) {
                float bv = Bs[k][nIdx + 16 * j];
                acc[0][j] += a0 * bv;
                acc[1][j] += a1 * bv;
                acc[2][j] += a2 * bv;
            }
        }
    }
    float* po = part + (size_t)blockIdx.y * BB * N + nt * 128;
#pragma unroll
    for (int i = 0; i < 3; ++i) {
        int m = 3 * mIdx + i;
#pragma unroll
        for (int j = 0; j < 8; ++j)
            po[(size_t)m * N + nIdx + 16 * j] = acc[i][j];
    }
}

// ---------------- reduce partials + bias -----------------------------
// mode 0: +bias[n]; mode 1: +bias[i] (per-row matrix, N==768); mode 2: none
__global__ void k_reduce(const float* __restrict__ bias, float* __restrict__ out,
                         int N, int KS, int mode) {
    int i = blockIdx.x * 256 + threadIdx.x;
    if (i >= BB * N) return;
    float s = 0.f;
    for (int ks = 0; ks < KS; ++ks) s += g_part[(size_t)ks * BB * N + i];
    if (mode == 0) s += bias[i % N];
    else if (mode == 1) s += bias[i];
    out[i] = s;
}

// ---------------- fused attention: scores -> softmax -> hbar ---------
__global__ void __launch_bounds__(256, 4)
k_attn(const float* __restrict__ hist) {
    __shared__ float Rs[DD];
    __shared__ float sc[104];
    __shared__ float red[2];
    const int b = blockIdx.x, tid = threadIdx.x;
    const int wid = tid >> 5, lane = tid & 31;
    const float* hb = hist + (size_t)b * LDH;

#pragma unroll
    for (int j = 0; j < 3; ++j) Rs[tid + 256 * j] = g_R[b * DD + tid + 256 * j];
    __syncthreads();

    for (int h = wid; h < HH; h += 8) {
        const float* row = hb + h * DD;
        float s = 0.f;
#pragma unroll 6
        for (int d = lane; d < DD; d += 32) s += row[d] * Rs[d];
#pragma unroll
        for (int o = 16; o; o >>= 1) s += __shfl_down_sync(0xffffffffu, s, o);
        if (lane == 0) sc[h] = s * (1.0f / 16.0f);
    }
    __syncthreads();

    if (wid == 0) {                                 // softmax stats on warp 0
        float v0 = sc[lane];
        float v1 = sc[lane + 32];
        float v2 = sc[lane + 64];
        float v3 = (lane + 96 < HH) ? sc[lane + 96] : -1e30f;
        float m = fmaxf(fmaxf(v0, v1), fmaxf(v2, v3));
#pragma unroll
        for (int o = 16; o; o >>= 1) m = fmaxf(m, __shfl_xor_sync(0xffffffffu, m, o));
        float e = __expf(v0 - m) + __expf(v1 - m) + __expf(v2 - m) +
                  ((lane + 96 < HH) ? __expf(v3 - m) : 0.f);
#pragma unroll
        for (int o = 16; o; o >>= 1) e += __shfl_xor_sync(0xffffffffu, e, o);
        if (lane == 0) { red[0] = m; red[1] = 1.0f / e; }
    }
    __syncthreads();
    if (tid < HH) sc[tid] = __expf(sc[tid] - red[0]) * red[1];
    __syncthreads();

    float s0 = 0.f, s1 = 0.f, s2 = 0.f;
    const float* p = hb + tid;
#pragma unroll 4
    for (int h = 0; h < HH; ++h) {
        float a = sc[h];
        s0 += a * p[h * DD];
        s1 += a * p[h * DD + 256];
        s2 += a * p[h * DD + 512];
    }
    g_hbar[b * DD + tid]       = s0;
    g_hbar[b * DD + tid + 256] = s1;
    g_hbar[b * DD + tid + 512] = s2;
}

// ---------------- broadcast to (B, N, D) -----------------------------
__global__ void k_bcast(float4* __restrict__ out) {
    int i = blockIdx.x * blockDim.x + threadIdx.x;
    const int D4 = DD / 4;
    int d4 = i % D4;
    int b = i / (D4 * NN);
    out[i] = ((const float4*)g_outb)[b * D4 + d4];
}

// ---------------- launch ---------------------------------------------
extern "C" void kernel_launch(void* const* d_in, const int* in_sizes, int n_in,
                              void* d_out, int out_size) {
    (void)in_sizes; (void)n_in; (void)out_size;
    const float* hist = (const float*)d_in[0];
    const float* Wl = (const float*)d_in[2];
    const float* bl = (const float*)d_in[3];
    const float* Wr = (const float*)d_in[4];
    const float* WK = (const float*)d_in[5];
    const float* WQ = (const float*)d_in[6];
    const float* bQ = (const float*)d_in[7];

    void *p_neigh, *p_bias, *p_u, *p_Q, *p_P, *p_R, *p_hbar, *p_outb,
         *p_part, *p_Wrt, *p_WKt;
    cudaGetSymbolAddress(&p_neigh, g_neigh);
    cudaGetSymbolAddress(&p_bias, g_bias);
    cudaGetSymbolAddress(&p_u, g_u);
    cudaGetSymbolAddress(&p_Q, g_Qv);
    cudaGetSymbolAddress(&p_P, g_P);
    cudaGetSymbolAddress(&p_R, g_R);
    cudaGetSymbolAddress(&p_hbar, g_hbar);
    cudaGetSymbolAddress(&p_outb, g_outb);
    cudaGetSymbolAddress(&p_part, g_part);
    cudaGetSymbolAddress(&p_Wrt, g_Wrt);
    cudaGetSymbolAddress(&p_WKt, g_WKt);
    float* part = (float*)p_part;

    dim3 tb(32, 8);
    k_transpose<<<dim3(DD / 32, DD / 32), tb>>>(Wr, (float*)p_Wrt, DD, DD);
    k_transpose<<<dim3(DD / 32, AA / 32), tb>>>(WK, (float*)p_WKt, AA, DD);
    k_neigh<<<BB, DD>>>(hist);

    // bias = neigh @ Wl^T + bl
    k_sgemm<<<dim3(6, 6), 512>>>((const float*)p_neigh, DD, Wl, part, DD, DD);
    k_reduce<<<(BB * DD + 255) / 256, 256>>>(bl, (float*)p_bias, DD, 6, 0);
    // u = hist[:,0,:] @ Wr^T + bias
    k_sgemm<<<dim3(6, 6), 512>>>(hist, LDH, Wr, part, DD, DD);
    k_reduce<<<(BB * DD + 255) / 256, 256>>>((const float*)p_bias, (float*)p_u, DD, 6, 1);
    // Q = u @ WQ^T + bQ
    k_sgemm<<<dim3(2, 6), 512>>>((const float*)p_u, DD, WQ, part, AA, DD);
    k_reduce<<<(BB * AA + 255) / 256, 256>>>(bQ, (float*)p_Q, AA, 6, 0);
    // P = Q @ WK   (B = WK^T rows)
    k_sgemm<<<dim3(6, 4), 512>>>((const float*)p_Q, AA, (const float*)p_WKt, part, DD, AA);
    k_reduce<<<(BB * DD + 255) / 256, 256>>>(nullptr, (float*)p_P, DD, 4, 2);
    // R = P @ Wr   (B = Wr^T rows)
    k_sgemm<<<dim3(6, 6), 512>>>((const float*)p_P, DD, (const float*)p_Wrt, part, DD, DD);
    k_reduce<<<(BB * DD + 255) / 256, 256>>>(nullptr, (float*)p_R, DD, 6, 2);

    // scores -> softmax -> hbar (per-batch fused)
    k_attn<<<BB, 256>>>(hist);

    // out = hbar @ Wr^T + bias
    k_sgemm<<<dim3(6, 6), 512>>>((const float*)p_hbar, DD, Wr, part, DD, DD);
    k_reduce<<<(BB * DD + 255) / 256, 256>>>((const float*)p_bias, (float*)p_outb, DD, 6, 1);

    k_bcast<<<(BB * NN * DD / 4) / 256, 256>>>((float4*)d_out);
}

// round 8
// speedup vs baseline: 6.0771x; 1.5440x over previous
#include <cuda_runtime.h>
#include <cstdint>

#define BB 96
#define HH 100
#define NN 128
#define DD 768
#define AA 256
#define LDH (HH * DD)      // hist batch stride
#define PS  (BB * DD)      // 73728, partial slot stride (N=768 max)

// ---------------- scratch ----------------
__device__ float g_neigh[BB * DD];
__device__ float g_bias [BB * DD];
__device__ float g_u    [BB * DD];
__device__ float g_Qv   [BB * AA];
__device__ float g_P    [BB * DD];
__device__ float g_R    [BB * DD];
__device__ float g_hbar [BB * DD];
__device__ float g_outb [BB * DD];
__device__ float g_part [48 * PS];   // up to 2 jobs x 24 K-slots
__device__ float g_Wrt  [DD * DD];
__device__ float g_WKt  [DD * AA];

// ---------------- transpose: out[C x R] = in[R x C]^T ----------------
__global__ void k_transpose(const float* __restrict__ in, float* __restrict__ out,
                            int R, int C) {
    __shared__ float t[32][33];
    int c0 = blockIdx.x * 32, r0 = blockIdx.y * 32;
    int x = threadIdx.x, y = threadIdx.y;          // 32 x 8
#pragma unroll
    for (int i = 0; i < 4; ++i)
        t[y + 8 * i][x] = in[(size_t)(r0 + y + 8 * i) * C + c0 + x];
    __syncthreads();
#pragma unroll
    for (int i = 0; i < 4; ++i)
        out[(size_t)(c0 + y + 8 * i) * R + r0 + x] = t[x][y + 8 * i];
}

// ---------------- neigh = mean_{h<96} hist[b,h,:] ----------------
__global__ void k_neigh(const float* __restrict__ hist) {
    int b = blockIdx.x, d = threadIdx.x;           // 768 threads
    const float* p = hist + (size_t)b * LDH + d;
    float s = 0.f;
#pragma unroll 8
    for (int h = 0; h < BB; ++h) s += p[h * DD];
    g_neigh[b * DD + d] = s * (1.0f / BB);
}

// ---------------- K-split GEMM, single 32-wide k-chunk per block -----
// part[slot][96][N] = A[96 x K] . B-rows[N x K] over k in [y*32, y*32+32)
// slot = z*24 + y. Two independent jobs selectable via blockIdx.z.
__global__ void __launch_bounds__(512, 2)
k_sgemm(const float* __restrict__ A0, int lda0, const float* __restrict__ B0,
        const float* __restrict__ A1, int lda1, const float* __restrict__ B1,
        float* __restrict__ part, int N, int K) {
    __shared__ float As[32][99];
    __shared__ float Bs[32][129];
    const int tid = threadIdx.x;
    const int nt = blockIdx.x;
    const int kb = blockIdx.y * 32;
    const int z = blockIdx.z;
    const float* A = z ? A1 : A0;
    const float* B = z ? B1 : B0;
    const int lda = z ? lda1 : lda0;
    const int mIdx = tid >> 4;
    const int nIdx = tid & 15;

    // load A (96x32) and B (128x32) chunks
    float2 va[3], vb[4];
#pragma unroll
    for (int j = 0; j < 3; ++j) {
        int idx = tid + 512 * j; int m = idx >> 4, c = idx & 15;
        va[j] = *(const float2*)(A + (size_t)m * lda + kb + 2 * c);
    }
#pragma unroll
    for (int j = 0; j < 4; ++j) {
        int idx = tid + 512 * j; int n = idx >> 4, c = idx & 15;
        vb[j] = *(const float2*)(B + (size_t)(nt * 128 + n) * K + kb + 2 * c);
    }
#pragma unroll
    for (int j = 0; j < 3; ++j) {
        int idx = tid + 512 * j; int m = idx >> 4, c = idx & 15;
        As[2 * c][m] = va[j].x; As[2 * c + 1][m] = va[j].y;
    }
#pragma unroll
    for (int j = 0; j < 4; ++j) {
        int idx = tid + 512 * j; int n = idx >> 4, c = idx & 15;
        Bs[2 * c][n] = vb[j].x; Bs[2 * c + 1][n] = vb[j].y;
    }
    __syncthreads();

    float acc[3][8];
#pragma unroll
    for (int i = 0; i < 3; ++i)
#pragma unroll
        for (int j = 0; j < 8; ++j) acc[i][j] = 0.f;
#pragma unroll
    for (int k = 0; k < 32; ++k) {
        float a0 = As[k][3 * mIdx], a1 = As[k][3 * mIdx + 1], a2 = As[k][3 * mIdx + 2];
#pragma unroll
        for (int j = 0; j < 8; ++j) {
            float bv = Bs[k][nIdx + 16 * j];
            acc[0][j] += a0 * bv;
            acc[1][j] += a1 * bv;
            acc[2][j] += a2 * bv;
        }
    }
    float* po = part + (size_t)(z * 24 + blockIdx.y) * BB * N + nt * 128;
#pragma unroll
    for (int i = 0; i < 3; ++i) {
        int m = 3 * mIdx + i;
#pragma unroll
        for (int j = 0; j < 8; ++j)
            po[(size_t)m * N + nIdx + 16 * j] = acc[i][j];
    }
}

// ---------------- generic reduce: out = sum partials (+bias) ---------
// mode 0: +bias[n]; mode 1: +bias[i]; mode 2: none
__global__ void k_reduce(const float* __restrict__ bias, float* __restrict__ out,
                         int N, int KS, int mode) {
    int i = blockIdx.x * 256 + threadIdx.x;
    if (i >= BB * N) return;
    float s = 0.f;
    for (int ks = 0; ks < KS; ++ks) s += g_part[(size_t)ks * BB * N + i];
    if (mode == 0) s += bias[i % N];
    else if (mode == 1) s += bias[i];
    out[i] = s;
}

// ---------------- fused reduce for combined launch -------------------
// bias = sum(slots 0..23) + bl[n];  u = sum(slots 24..47) + bias
__global__ void k_reduce2(const float* __restrict__ bl) {
    int i = blockIdx.x * 256 + threadIdx.x;
    if (i >= BB * DD) return;
    float sb = 0.f, su = 0.f;
#pragma unroll 4
    for (int ks = 0; ks < 24; ++ks) {
        sb += g_part[(size_t)ks * PS + i];
        su += g_part[(size_t)(24 + ks) * PS + i];
    }
    float bv = sb + bl[i % DD];
    g_bias[i] = bv;
    g_u[i] = su + bv;
}

// ---------------- fused attention: scores -> softmax -> hbar ---------
__global__ void __launch_bounds__(256, 4)
k_attn(const float* __restrict__ hist) {
    __shared__ float Rs[DD];
    __shared__ float sc[104];
    __shared__ float red[2];
    const int b = blockIdx.x, tid = threadIdx.x;
    const int wid = tid >> 5, lane = tid & 31;
    const float* hb = hist + (size_t)b * LDH;

#pragma unroll
    for (int j = 0; j < 3; ++j) Rs[tid + 256 * j] = g_R[b * DD + tid + 256 * j];
    __syncthreads();

    for (int h = wid; h < HH; h += 8) {
        const float* row = hb + h * DD;
        float s = 0.f;
#pragma unroll 6
        for (int d = lane; d < DD; d += 32) s += row[d] * Rs[d];
#pragma unroll
        for (int o = 16; o; o >>= 1) s += __shfl_down_sync(0xffffffffu, s, o);
        if (lane == 0) sc[h] = s * (1.0f / 16.0f);
    }
    __syncthreads();

    if (wid == 0) {
        float v0 = sc[lane];
        float v1 = sc[lane + 32];
        float v2 = sc[lane + 64];
        float v3 = (lane + 96 < HH) ? sc[lane + 96] : -1e30f;
        float m = fmaxf(fmaxf(v0, v1), fmaxf(v2, v3));
#pragma unroll
        for (int o = 16; o; o >>= 1) m = fmaxf(m, __shfl_xor_sync(0xffffffffu, m, o));
        float e = __expf(v0 - m) + __expf(v1 - m) + __expf(v2 - m) +
                  ((lane + 96 < HH) ? __expf(v3 - m) : 0.f);
#pragma unroll
        for (int o = 16; o; o >>= 1) e += __shfl_xor_sync(0xffffffffu, e, o);
        if (lane == 0) { red[0] = m; red[1] = 1.0f / e; }
    }
    __syncthreads();
    if (tid < HH) sc[tid] = __expf(sc[tid] - red[0]) * red[1];
    __syncthreads();

    float s0 = 0.f, s1 = 0.f, s2 = 0.f;
    const float* p = hb + tid;
#pragma unroll 4
    for (int h = 0; h < HH; ++h) {
        float a = sc[h];
        s0 += a * p[h * DD];
        s1 += a * p[h * DD + 256];
        s2 += a * p[h * DD + 512];
    }
    g_hbar[b * DD + tid]       = s0;
    g_hbar[b * DD + tid + 256] = s1;
    g_hbar[b * DD + tid + 512] = s2;
}

// ---------------- broadcast to (B, N, D) -----------------------------
__global__ void k_bcast(float4* __restrict__ out) {
    int i = blockIdx.x * blockDim.x + threadIdx.x;
    const int D4 = DD / 4;
    int d4 = i % D4;
    int b = i / (D4 * NN);
    out[i] = ((const float4*)g_outb)[b * D4 + d4];
}

// ---------------- launch ---------------------------------------------
extern "C" void kernel_launch(void* const* d_in, const int* in_sizes, int n_in,
                              void* d_out, int out_size) {
    (void)in_sizes; (void)n_in; (void)out_size;
    const float* hist = (const float*)d_in[0];
    const float* Wl = (const float*)d_in[2];
    const float* bl = (const float*)d_in[3];
    const float* Wr = (const float*)d_in[4];
    const float* WK = (const float*)d_in[5];
    const float* WQ = (const float*)d_in[6];
    const float* bQ = (const float*)d_in[7];

    void *p_neigh, *p_u, *p_Q, *p_P, *p_R, *p_hbar, *p_outb,
         *p_part, *p_Wrt, *p_WKt, *p_bias;
    cudaGetSymbolAddress(&p_neigh, g_neigh);
    cudaGetSymbolAddress(&p_bias, g_bias);
    cudaGetSymbolAddress(&p_u, g_u);
    cudaGetSymbolAddress(&p_Q, g_Qv);
    cudaGetSymbolAddress(&p_P, g_P);
    cudaGetSymbolAddress(&p_R, g_R);
    cudaGetSymbolAddress(&p_hbar, g_hbar);
    cudaGetSymbolAddress(&p_outb, g_outb);
    cudaGetSymbolAddress(&p_part, g_part);
    cudaGetSymbolAddress(&p_Wrt, g_Wrt);
    cudaGetSymbolAddress(&p_WKt, g_WKt);
    float* part = (float*)p_part;

    dim3 tb(32, 8);
    k_transpose<<<dim3(DD / 32, DD / 32), tb>>>(Wr, (float*)p_Wrt, DD, DD);
    k_transpose<<<dim3(DD / 32, AA / 32), tb>>>(WK, (float*)p_WKt, AA, DD);
    k_neigh<<<BB, DD>>>(hist);

    // combined: z=0 bias_pre = neigh@Wl^T; z=1 u_pre = hist0@Wr^T
    k_sgemm<<<dim3(6, 24, 2), 512>>>((const float*)p_neigh, DD, Wl,
                                     hist, LDH, Wr, part, DD, DD);
    k_reduce2<<<(BB * DD + 255) / 256, 256>>>(bl);

    // Q = u @ WQ^T + bQ   (N=256, K=768)
    k_sgemm<<<dim3(2, 24, 1), 512>>>((const float*)p_u, DD, WQ,
                                     nullptr, 0, nullptr, part, AA, DD);
    k_reduce<<<(BB * AA + 255) / 256, 256>>>(bQ, (float*)p_Q, AA, 24, 0);

    // P = Q @ WK          (N=768, K=256, B = WK^T rows)
    k_sgemm<<<dim3(6, 8, 1), 512>>>((const float*)p_Q, AA, (const float*)p_WKt,
                                    nullptr, 0, nullptr, part, DD, AA);
    k_reduce<<<(BB * DD + 255) / 256, 256>>>(nullptr, (float*)p_P, DD, 8, 2);

    // R = P @ Wr          (N=768, K=768, B = Wr^T rows)
    k_sgemm<<<dim3(6, 24, 1), 512>>>((const float*)p_P, DD, (const float*)p_Wrt,
                                     nullptr, 0, nullptr, part, DD, DD);
    k_reduce<<<(BB * DD + 255) / 256, 256>>>(nullptr, (float*)p_R, DD, 24, 2);

    // scores -> softmax -> hbar
    k_attn<<<BB, 256>>>(hist);

    // out = hbar @ Wr^T + bias
    k_sgemm<<<dim3(6, 24, 1), 512>>>((const float*)p_hbar, DD, Wr,
                                     nullptr, 0, nullptr, part, DD, DD);
    k_reduce<<<(BB * DD + 255) / 256, 256>>>((const float*)p_bias, (float*)p_outb,
                                             DD, 24, 1);

    k_bcast<<<(BB * NN * DD / 4) / 256, 256>>>((float4*)d_out);
}

// round 10
// speedup vs baseline: 6.9863x; 1.1496x over previous
#include <cuda_runtime.h>
#include <cstdint>

#define BB 96
#define HH 100
#define NN 128
#define DD 768
#define AA 256
#define LDH (HH * DD)      // hist batch stride
#define PS  (BB * DD)      // partial slot stride (N=768)

// ---------------- scratch ----------------
__device__ float g_neigh[BB * DD];
__device__ float g_bias [BB * DD];
__device__ float g_u    [BB * DD];
__device__ float g_Qv   [BB * AA];
__device__ float g_P    [BB * DD];
__device__ float g_R    [BB * DD];
__device__ float g_hbar [BB * DD];
__device__ float g_part [48 * PS];   // 2 jobs x 24 K-slots max

// ---------------- neigh = mean_{h<96} hist[b,h,:] ----------------
__global__ void k_neigh(const float* __restrict__ hist) {
    int b = blockIdx.x, d = threadIdx.x;           // 768 threads
    const float* p = hist + (size_t)b * LDH + d;
    float s = 0.f;
#pragma unroll 8
    for (int h = 0; h < BB; ++h) s += p[h * DD];
    g_neigh[b * DD + d] = s * (1.0f / BB);
}

// ======== shared GEMM body: compute from As/Bs, write partials =======
// thread tile 6m x 4n; 16 x 32 thread grid.
#define GEMM_COMPUTE_STORE()                                                  \
    __syncthreads();                                                          \
    const int mI = tid >> 5, nI = tid & 31;                                   \
    float acc[6][4];                                                          \
    _Pragma("unroll") for (int i = 0; i < 6; ++i)                             \
    _Pragma("unroll") for (int j = 0; j < 4; ++j) acc[i][j] = 0.f;            \
    _Pragma("unroll") for (int k = 0; k < 32; ++k) {                          \
        float2 a01 = *(const float2*)&As[k][6 * mI];                          \
        float2 a23 = *(const float2*)&As[k][6 * mI + 2];                      \
        float2 a45 = *(const float2*)&As[k][6 * mI + 4];                      \
        float4 bv  = *(const float4*)&Bs[k][4 * nI];                          \
        float am[6] = {a01.x, a01.y, a23.x, a23.y, a45.x, a45.y};             \
        _Pragma("unroll") for (int i = 0; i < 6; ++i) {                       \
            acc[i][0] += am[i] * bv.x;  acc[i][1] += am[i] * bv.y;            \
            acc[i][2] += am[i] * bv.z;  acc[i][3] += am[i] * bv.w;            \
        }                                                                     \
    }                                                                         \
    float* po = part + (size_t)slot * BB * N + blockIdx.x * 128;              \
    _Pragma("unroll") for (int i = 0; i < 6; ++i) {                           \
        int m = 6 * mI + i;                                                   \
        float4 v = make_float4(acc[i][0], acc[i][1], acc[i][2], acc[i][3]);   \
        *(float4*)&po[(size_t)m * N + 4 * nI] = v;                            \
    }

// ---- T layout: out[m,n] = sum_k A[m,k] * B[n,k] (B rows n, k-contig)
__global__ void __launch_bounds__(512, 2)
k_sgemmT(const float* __restrict__ A0, int lda0, const float* __restrict__ B0,
         const float* __restrict__ A1, int lda1, const float* __restrict__ B1,
         float* __restrict__ part, int N, int K) {
    __shared__ float As[32][98];
    __shared__ float Bs[32][132];
    const int tid = threadIdx.x;
    const int kb = blockIdx.y * 32;
    const int z = blockIdx.z;
    const int slot = z * 24 + blockIdx.y;
    const float* A = z ? A1 : A0;
    const float* B = z ? B1 : B0;
    const int lda = z ? lda1 : lda0;

    float2 va[3], vb[4];
#pragma unroll
    for (int j = 0; j < 3; ++j) {
        int idx = tid + 512 * j; int m = idx >> 4, c = idx & 15;
        va[j] = *(const float2*)(A + (size_t)m * lda + kb + 2 * c);
    }
#pragma unroll
    for (int j = 0; j < 4; ++j) {
        int idx = tid + 512 * j; int n = idx >> 4, c = idx & 15;
        vb[j] = *(const float2*)(B + (size_t)(blockIdx.x * 128 + n) * K + kb + 2 * c);
    }
#pragma unroll
    for (int j = 0; j < 3; ++j) {
        int idx = tid + 512 * j; int m = idx >> 4, c = idx & 15;
        As[2 * c][m] = va[j].x; As[2 * c + 1][m] = va[j].y;
    }
#pragma unroll
    for (int j = 0; j < 4; ++j) {
        int idx = tid + 512 * j; int n = idx >> 4, c = idx & 15;
        Bs[2 * c][n] = vb[j].x; Bs[2 * c + 1][n] = vb[j].y;
    }
    GEMM_COMPUTE_STORE()
}

// ---- NT layout: out[m,n] = sum_k A[m,k] * B[k,n] (B rows k, n-contig)
__global__ void __launch_bounds__(512, 2)
k_sgemmNT(const float* __restrict__ A, int lda, const float* __restrict__ B,
          int ldb, float* __restrict__ part, int N, int K) {
    __shared__ float As[32][98];
    __shared__ float Bs[32][132];
    const int tid = threadIdx.x;
    const int kb = blockIdx.y * 32;
    const int slot = blockIdx.y;

    float2 va[3];
    float4 wb[2];
#pragma unroll
    for (int j = 0; j < 3; ++j) {
        int idx = tid + 512 * j; int m = idx >> 4, c = idx & 15;
        va[j] = *(const float2*)(A + (size_t)m * lda + kb + 2 * c);
    }
#pragma unroll
    for (int j = 0; j < 2; ++j) {
        int vidx = tid + 512 * j; int k = vidx >> 5, nv = vidx & 31;
        wb[j] = *(const float4*)(B + (size_t)(kb + k) * ldb + blockIdx.x * 128 + 4 * nv);
    }
#pragma unroll
    for (int j = 0; j < 3; ++j) {
        int idx = tid + 512 * j; int m = idx >> 4, c = idx & 15;
        As[2 * c][m] = va[j].x; As[2 * c + 1][m] = va[j].y;
    }
#pragma unroll
    for (int j = 0; j < 2; ++j) {
        int vidx = tid + 512 * j; int k = vidx >> 5, nv = vidx & 31;
        *(float4*)&Bs[k][4 * nv] = wb[j];
    }
    GEMM_COMPUTE_STORE()
}

// ---------------- generic reduce: out = sum partials (+bias) ---------
// mode 0: +bias[n]; mode 2: none
__global__ void k_reduce(const float* __restrict__ bias, float* __restrict__ out,
                         int N, int KS, int mode) {
    int i = blockIdx.x * 256 + threadIdx.x;
    if (i >= BB * N) return;
    float s = 0.f;
    for (int ks = 0; ks < KS; ++ks) s += g_part[(size_t)ks * BB * N + i];
    if (mode == 0) s += bias[i % N];
    out[i] = s;
}

// ---- fused: bias = sum(0..23)+bl; u = sum(24..47)+bias --------------
__global__ void k_reduce2(const float* __restrict__ bl) {
    int i = blockIdx.x * 256 + threadIdx.x;
    if (i >= BB * DD) return;
    float sb = 0.f, su = 0.f;
#pragma unroll 4
    for (int ks = 0; ks < 24; ++ks) {
        sb += g_part[(size_t)ks * PS + i];
        su += g_part[(size_t)(24 + ks) * PS + i];
    }
    float bv = sb + bl[i % DD];
    g_bias[i] = bv;
    g_u[i] = su + bv;
}

// ---- final: out_flat = sum partials + bias, broadcast over N --------
__global__ void k_reduce_bcast(float* __restrict__ out) {
    int i = blockIdx.x * 256 + threadIdx.x;
    if (i >= BB * DD) return;
    float s = 0.f;
#pragma unroll 4
    for (int ks = 0; ks < 24; ++ks) s += g_part[(size_t)ks * PS + i];
    s += g_bias[i];
    int b = i / DD, d = i - b * DD;
    float* po = out + (size_t)b * NN * DD + d;
#pragma unroll 8
    for (int n = 0; n < NN; ++n) po[n * DD] = s;
}

// ---------------- fused attention: scores -> softmax -> hbar ---------
__global__ void __launch_bounds__(256, 4)
k_attn(const float* __restrict__ hist) {
    __shared__ float Rs[DD];
    __shared__ float sc[104];
    __shared__ float red[2];
    const int b = blockIdx.x, tid = threadIdx.x;
    const int wid = tid >> 5, lane = tid & 31;
    const float* hb = hist + (size_t)b * LDH;

#pragma unroll
    for (int j = 0; j < 3; ++j) Rs[tid + 256 * j] = g_R[b * DD + tid + 256 * j];
    __syncthreads();

    for (int h = wid; h < HH; h += 8) {
        const float* row = hb + h * DD;
        float s = 0.f;
#pragma unroll 6
        for (int d = lane; d < DD; d += 32) s += row[d] * Rs[d];
#pragma unroll
        for (int o = 16; o; o >>= 1) s += __shfl_down_sync(0xffffffffu, s, o);
        if (lane == 0) sc[h] = s * (1.0f / 16.0f);
    }
    __syncthreads();

    if (wid == 0) {
        float v0 = sc[lane];
        float v1 = sc[lane + 32];
        float v2 = sc[lane + 64];
        float v3 = (lane + 96 < HH) ? sc[lane + 96] : -1e30f;
        float m = fmaxf(fmaxf(v0, v1), fmaxf(v2, v3));
#pragma unroll
        for (int o = 16; o; o >>= 1) m = fmaxf(m, __shfl_xor_sync(0xffffffffu, m, o));
        float e = __expf(v0 - m) + __expf(v1 - m) + __expf(v2 - m) +
                  ((lane + 96 < HH) ? __expf(v3 - m) : 0.f);
#pragma unroll
        for (int o = 16; o; o >>= 1) e += __shfl_xor_sync(0xffffffffu, e, o);
        if (lane == 0) { red[0] = m; red[1] = 1.0f / e; }
    }
    __syncthreads();
    if (tid < HH) sc[tid] = __expf(sc[tid] - red[0]) * red[1];
    __syncthreads();

    float s0 = 0.f, s1 = 0.f, s2 = 0.f;
    const float* p = hb + tid;
#pragma unroll 4
    for (int h = 0; h < HH; ++h) {
        float a = sc[h];
        s0 += a * p[h * DD];
        s1 += a * p[h * DD + 256];
        s2 += a * p[h * DD + 512];
    }
    g_hbar[b * DD + tid]       = s0;
    g_hbar[b * DD + tid + 256] = s1;
    g_hbar[b * DD + tid + 512] = s2;
}

// ---------------- launch ---------------------------------------------
extern "C" void kernel_launch(void* const* d_in, const int* in_sizes, int n_in,
                              void* d_out, int out_size) {
    (void)in_sizes; (void)n_in; (void)out_size;
    const float* hist = (const float*)d_in[0];
    const float* Wl = (const float*)d_in[2];
    const float* bl = (const float*)d_in[3];
    const float* Wr = (const float*)d_in[4];
    const float* WK = (const float*)d_in[5];
    const float* WQ = (const float*)d_in[6];
    const float* bQ = (const float*)d_in[7];

    void *p_neigh, *p_u, *p_Q, *p_P, *p_R, *p_hbar, *p_part;
    cudaGetSymbolAddress(&p_neigh, g_neigh);
    cudaGetSymbolAddress(&p_u, g_u);
    cudaGetSymbolAddress(&p_Q, g_Qv);
    cudaGetSymbolAddress(&p_P, g_P);
    cudaGetSymbolAddress(&p_R, g_R);
    cudaGetSymbolAddress(&p_hbar, g_hbar);
    cudaGetSymbolAddress(&p_part, g_part);
    float* part = (float*)p_part;

    k_neigh<<<BB, DD>>>(hist);

    // z=0: bias_pre = neigh@Wl^T; z=1: u_pre = hist0@Wr^T
    k_sgemmT<<<dim3(6, 24, 2), 512>>>((const float*)p_neigh, DD, Wl,
                                      hist, LDH, Wr, part, DD, DD);
    k_reduce2<<<(BB * DD + 255) / 256, 256>>>(bl);

    // Q = u @ WQ^T + bQ   (N=256, K=768)
    k_sgemmT<<<dim3(2, 24, 1), 512>>>((const float*)p_u, DD, WQ,
                                      nullptr, 0, nullptr, part, AA, DD);
    k_reduce<<<(BB * AA + 255) / 256, 256>>>(bQ, (float*)p_Q, AA, 24, 0);

    // P = Q @ WK          (N=768, K=256; B rows k = WK rows)
    k_sgemmNT<<<dim3(6, 8, 1), 512>>>((const float*)p_Q, AA, WK, DD,
                                      part, DD, AA);
    k_reduce<<<(BB * DD + 255) / 256, 256>>>(nullptr, (float*)p_P, DD, 8, 2);

    // R = P @ Wr          (N=768, K=768; B rows k = Wr rows)
    k_sgemmNT<<<dim3(6, 24, 1), 512>>>((const float*)p_P, DD, Wr, DD,
                                       part, DD, DD);
    k_reduce<<<(BB * DD + 255) / 256, 256>>>(nullptr, (float*)p_R, DD, 24, 2);

    // scores -> softmax -> hbar
    k_attn<<<BB, 256>>>(hist);

    // out = hbar @ Wr^T + bias, broadcast over N
    k_sgemmT<<<dim3(6, 24, 1), 512>>>((const float*)p_hbar, DD, Wr,
                                      nullptr, 0, nullptr, part, DD, DD);
    k_reduce_bcast<<<(BB * DD + 255) / 256, 256>>>((float*)d_out);
}